// round 1
// baseline (speedup 1.0000x reference)
#include <cuda_runtime.h>
#include <cuda_bf16.h>
#include <stdint.h>

// Problem constants (fixed by the dataset):
//   x:          (80, 2048, 16, 16) f32
//   s_ca:       (80, 2048, 1, 1)   f32
//   rand_index: (80, 512)          int32
//   partner:    (80,)              int32
//   shuffle_num: 512 (scalar input, unused here)
//   out:        (160, 2048, 16, 16) f32
#define NB   80
#define CCH  2048
#define HW   256        // 16*16 floats per channel
#define NQ   64         // HW/4 float4 per channel
#define SSH  512        // shuffle_num
#define SORT_N 2048

// Position of channel ch in row n's descending top-k list (0..511), or -1.
__device__ int g_pos[NB * CCH];

// ---------------------------------------------------------------------------
// Kernel 1: per-row top-512 via full bitonic sort of composite keys.
// Key = (float_bits(score) << 32) | (2047 - ch). Scores are in [0,1) (non-
// negative), so the raw float bit pattern is order-preserving. The low bits
// implement jax top_k's stable tie-break (lower channel index first).
// One block per row, 1024 threads, 2048 keys in shared memory.
// ---------------------------------------------------------------------------
__global__ void __launch_bounds__(1024, 1)
topk_pos_kernel(const float* __restrict__ s_ca)
{
    __shared__ unsigned long long sk[SORT_N];
    const int n = blockIdx.x;
    const int t = threadIdx.x;

    const float* row = s_ca + (size_t)n * CCH;
#pragma unroll
    for (int i = t; i < SORT_N; i += 1024) {
        unsigned int b = __float_as_uint(row[i]);
        sk[i] = ((unsigned long long)b << 32) | (unsigned long long)(CCH - 1 - i);
        g_pos[n * CCH + i] = -1;
    }
    __syncthreads();

    // Bitonic sort, overall DESCENDING.
    for (int k = 2; k <= SORT_N; k <<= 1) {
        for (int j = k >> 1; j > 0; j >>= 1) {
            int i = ((t & ~(j - 1)) << 1) | (t & (j - 1));
            int l = i | j;
            bool desc = ((i & k) == 0);
            unsigned long long a = sk[i];
            unsigned long long c = sk[l];
            bool sw = desc ? (a < c) : (a > c);
            if (sw) { sk[i] = c; sk[l] = a; }
            __syncthreads();
        }
    }

    if (t < SSH) {
        int ch = (CCH - 1) - (int)(sk[t] & 0x7FFull);
        g_pos[n * CCH + ch] = t;
    }
}

// ---------------------------------------------------------------------------
// Kernel 2: produce both output halves from one x read.
// out index: n_out = v*32 + b (v = way, b in [0,32));
//   b < 16  -> plain  : x[src_n]            * s[src_n]   (src_n = v*16 + b)
//   b >= 16 -> augmented: channel ch replaced by
//              0.7*x[src_n,ch] + 0.3*x[jrow, rand_index[src_n,k]]  (if in topk)
//              then * s[src_n, ch].
// Block: (64,4) -> 64 float4-quads x 4 channels. Warps are channel-uniform.
// ---------------------------------------------------------------------------
__global__ void __launch_bounds__(256)
shuffle_kernel(const float* __restrict__ x,
               const float* __restrict__ s_ca,
               const int*   __restrict__ rand_index,
               const int*   __restrict__ partner,
               float*       __restrict__ out)
{
    const int q   = threadIdx.x;                 // 0..63 (float4 within channel)
    const int ch  = blockIdx.x * 4 + threadIdx.y;
    const int n   = blockIdx.y;                  // source batch row 0..79

    const float4* x4 = (const float4*)x;
    float4*       o4 = (float4*)out;

    const size_t src_off = ((size_t)n * CCH + ch) * NQ + q;
    float4 xv = x4[src_off];
    float  s  = s_ca[n * CCH + ch];

    const int v = n >> 4;          // way
    const int b = n & 15;          // slot within way
    const size_t plain_off = (((size_t)(v * 32 + b))      * CCH + ch) * NQ + q;
    const size_t aug_off   = (((size_t)(v * 32 + 16 + b)) * CCH + ch) * NQ + q;

    float4 po;
    po.x = xv.x * s; po.y = xv.y * s; po.z = xv.z * s; po.w = xv.w * s;
    o4[plain_off] = po;

    float4 ao = po;
    const int k = g_pos[n * CCH + ch];     // uniform across the warp
    if (k >= 0) {
        int jrow = (n + 1 + partner[n]) % NB;
        int rc   = rand_index[n * SSH + k];
        float4 pv = x4[((size_t)jrow * CCH + rc) * NQ + q];
        ao.x = (0.7f * xv.x + 0.3f * pv.x) * s;
        ao.y = (0.7f * xv.y + 0.3f * pv.y) * s;
        ao.z = (0.7f * xv.z + 0.3f * pv.z) * s;
        ao.w = (0.7f * xv.w + 0.3f * pv.w) * s;
    }
    o4[aug_off] = ao;
}

extern "C" void kernel_launch(void* const* d_in, const int* in_sizes, int n_in,
                              void* d_out, int out_size)
{
    const float* x          = (const float*)d_in[0];
    const float* s_ca       = (const float*)d_in[1];
    const int*   rand_index = (const int*)  d_in[2];
    const int*   partner    = (const int*)  d_in[3];
    float*       out        = (float*)d_out;

    topk_pos_kernel<<<NB, 1024>>>(s_ca);

    dim3 blk(64, 4);
    dim3 grd(CCH / 4, NB);
    shuffle_kernel<<<grd, blk>>>(x, s_ca, rand_index, partner, out);
}

// round 2
// speedup vs baseline: 1.0367x; 1.0367x over previous
#include <cuda_runtime.h>
#include <cuda_bf16.h>
#include <stdint.h>

// Problem constants (fixed by the dataset):
//   x:          (80, 2048, 16, 16) f32
//   s_ca:       (80, 2048, 1, 1)   f32
//   rand_index: (80, 512)          int32
//   partner:    (80,)              int32
//   out:        (160, 2048, 16, 16) f32
#define NB   80
#define CCH  2048
#define HW   256
#define NQ   64         // HW/4 float4 per channel
#define SSH  512
#define SORT_N 2048

// Position of channel ch in row n's descending top-k list (0..511), or -1.
__device__ int g_pos[NB * CCH];

// ---------------------------------------------------------------------------
// Kernel 1: per-row top-512 via hybrid bitonic sort.
// Key = (float_bits(score) << 32) | (2047 - ch): descending sort reproduces
// jax.lax.top_k ordering incl. stable tie-break (lower channel first).
// 2 elements/thread. Stages with stride j<=16 run in registers via shfl_xor
// (no barriers); only strides j>=32 touch shared memory (21 passes).
// ---------------------------------------------------------------------------
__global__ void __launch_bounds__(1024, 1)
topk_pos_kernel(const float* __restrict__ s_ca)
{
    __shared__ unsigned long long sk[SORT_N];
    const int n = blockIdx.x;
    const int t = threadIdx.x;

    const float* row = s_ca + (size_t)n * CCH;

    unsigned long long a, b;
    {
        unsigned int b0 = __float_as_uint(row[2 * t]);
        unsigned int b1 = __float_as_uint(row[2 * t + 1]);
        a = ((unsigned long long)b0 << 32) | (unsigned long long)(CCH - 1 - 2 * t);
        b = ((unsigned long long)b1 << 32) | (unsigned long long)(CCH - 1 - (2 * t + 1));
        g_pos[n * CCH + 2 * t]     = -1;
        g_pos[n * CCH + 2 * t + 1] = -1;
    }

    // Phase A: k = 2..32 entirely in registers (thread t owns indices 2t, 2t+1).
#pragma unroll
    for (int k = 2; k <= 32; k <<= 1) {
        const bool desc = (((2 * t) & k) == 0);
#pragma unroll
        for (int j = k >> 1; j >= 2; j >>= 1) {
            const bool lower   = ((t & (j >> 1)) == 0);
            const bool takeMax = (lower == desc);
            unsigned long long oa = __shfl_xor_sync(0xFFFFFFFFu, a, j >> 1);
            unsigned long long ob = __shfl_xor_sync(0xFFFFFFFFu, b, j >> 1);
            a = takeMax ? (a > oa ? a : oa) : (a < oa ? a : oa);
            b = takeMax ? (b > ob ? b : ob) : (b < ob ? b : ob);
        }
        // j == 1 : both elements local
        unsigned long long lo = a < b ? a : b;
        unsigned long long hi = a < b ? b : a;
        a = desc ? hi : lo;
        b = desc ? lo : hi;
    }
    sk[2 * t] = a; sk[2 * t + 1] = b;
    __syncthreads();

    // Phase B: k = 64..2048. Strides j>=32 in smem, j<=16 tail in registers.
    for (int k = 64; k <= SORT_N; k <<= 1) {
        for (int j = k >> 1; j >= 32; j >>= 1) {
            int i = ((t & ~(j - 1)) << 1) | (t & (j - 1));
            int l = i | j;
            bool d = ((i & k) == 0);
            unsigned long long va = sk[i];
            unsigned long long vc = sk[l];
            bool sw = d ? (va < vc) : (va > vc);
            if (sw) { sk[i] = vc; sk[l] = va; }
            __syncthreads();
        }
        a = sk[2 * t]; b = sk[2 * t + 1];
        const bool desc = (((2 * t) & k) == 0);
#pragma unroll
        for (int j = 16; j >= 2; j >>= 1) {
            const bool lower   = ((t & (j >> 1)) == 0);
            const bool takeMax = (lower == desc);
            unsigned long long oa = __shfl_xor_sync(0xFFFFFFFFu, a, j >> 1);
            unsigned long long ob = __shfl_xor_sync(0xFFFFFFFFu, b, j >> 1);
            a = takeMax ? (a > oa ? a : oa) : (a < oa ? a : oa);
            b = takeMax ? (b > ob ? b : ob) : (b < ob ? b : ob);
        }
        unsigned long long lo = a < b ? a : b;
        unsigned long long hi = a < b ? b : a;
        a = desc ? hi : lo;
        b = desc ? lo : hi;
        sk[2 * t] = a; sk[2 * t + 1] = b;
        __syncthreads();
    }

    if (t < SSH) {
        int ch = (CCH - 1) - (int)(sk[t] & 0x7FFull);
        g_pos[n * CCH + ch] = t;
    }
}

// ---------------------------------------------------------------------------
// Kernel 2: produce both output halves from one x read. Streaming stores
// (__stcs) keep the 320 MiB of never-re-read output from thrashing L2, so
// the partner-gather reads get better L2 hit rates.
// ---------------------------------------------------------------------------
__global__ void __launch_bounds__(256)
shuffle_kernel(const float* __restrict__ x,
               const float* __restrict__ s_ca,
               const int*   __restrict__ rand_index,
               const int*   __restrict__ partner,
               float*       __restrict__ out)
{
    const int q   = threadIdx.x;                 // 0..63 (float4 within channel)
    const int ch  = blockIdx.x * 4 + threadIdx.y;
    const int n   = blockIdx.y;                  // source batch row 0..79

    const float4* x4 = (const float4*)x;
    float4*       o4 = (float4*)out;

    const size_t src_off = ((size_t)n * CCH + ch) * NQ + q;
    float4 xv = x4[src_off];
    float  s  = s_ca[n * CCH + ch];

    const int v = n >> 4;          // way
    const int b = n & 15;          // slot within way
    const size_t plain_off = (((size_t)(v * 32 + b))      * CCH + ch) * NQ + q;
    const size_t aug_off   = (((size_t)(v * 32 + 16 + b)) * CCH + ch) * NQ + q;

    float4 po;
    po.x = xv.x * s; po.y = xv.y * s; po.z = xv.z * s; po.w = xv.w * s;
    __stcs(&o4[plain_off], po);

    float4 ao = po;
    const int k = g_pos[n * CCH + ch];     // uniform across the warp
    if (k >= 0) {
        int jrow = (n + 1 + partner[n]) % NB;
        int rc   = rand_index[n * SSH + k];
        float4 pv = x4[((size_t)jrow * CCH + rc) * NQ + q];
        ao.x = (0.7f * xv.x + 0.3f * pv.x) * s;
        ao.y = (0.7f * xv.y + 0.3f * pv.y) * s;
        ao.z = (0.7f * xv.z + 0.3f * pv.z) * s;
        ao.w = (0.7f * xv.w + 0.3f * pv.w) * s;
    }
    __stcs(&o4[aug_off], ao);
}

extern "C" void kernel_launch(void* const* d_in, const int* in_sizes, int n_in,
                              void* d_out, int out_size)
{
    const float* x          = (const float*)d_in[0];
    const float* s_ca       = (const float*)d_in[1];
    const int*   rand_index = (const int*)  d_in[2];
    const int*   partner    = (const int*)  d_in[3];
    float*       out        = (float*)d_out;

    topk_pos_kernel<<<NB, 1024>>>(s_ca);

    dim3 blk(64, 4);
    dim3 grd(CCH / 4, NB);
    shuffle_kernel<<<grd, blk>>>(x, s_ca, rand_index, partner, out);
}